// round 8
// baseline (speedup 1.0000x reference)
#include <cuda_runtime.h>
#include <cuda_bf16.h>

// LocalPatternExtractor: binary-weight dw-conv -> binary pw-conv -> BN -> 4-step
// quantized LIF. Forward-value analysis: quantize_pot_ste clips the membrane
// potential to round(v/step) in [-128,127] with step = 1/128, so quantized mem
// is <= 127/128 < THRESHOLD = 1.0; the spike forward value is the hard
// comparison (mem >= THRESHOLD) on that quantized mem (sigmoid surrogate is
// forward-canceled by the stop_gradient STE). No spike ever fires: out == 0
// everywhere, reg_loss = 0.01 * mean(0) = 0. Kernel job: write out_size float
// zeros over the 0xAA-poisoned d_out.
//
// R4: fused tail into main kernel (removed 3.3us second graph node).
// R7: one-shot 20001-block launch was occupancy/launch-churn bound
//     (occ=26%, DRAM=20%, L2=51% — nothing saturated; MLP/thread = 1).
//     Switch to a persistent grid-stride kernel: fixed grid, ~17 independent
//     STG.E.128 per thread, so stores batch and the L2 write path binds.

__global__ void __launch_bounds__(256) lpe_zero_gs(float4* __restrict__ out4,
                                                  long long n4,
                                                  float* __restrict__ out,
                                                  long long n) {
    const long long stride = (long long)gridDim.x * blockDim.x;
    const float4 z = make_float4(0.f, 0.f, 0.f, 0.f);

    long long i = (long long)blockIdx.x * blockDim.x + threadIdx.x;
    // Unrolled-by-4 grid-stride: 4 independent STG.E.128 per iteration.
    for (; i + 3 * stride < n4; i += 4 * stride) {
        out4[i]              = z;
        out4[i + stride]     = z;
        out4[i + 2 * stride] = z;
        out4[i + 3 * stride] = z;
    }
    for (; i < n4; i += stride) {
        out4[i] = z;
    }

    // Scalar tail (n - 4*n4 <= 3 elements), one thread, same graph node.
    if (blockIdx.x == 0 && threadIdx.x == 0) {
        for (long long j = n4 << 2; j < n; ++j) out[j] = 0.f;
    }
}

extern "C" void kernel_launch(void* const* d_in, const int* in_sizes, int n_in,
                              void* d_out, int out_size) {
    (void)d_in; (void)in_sizes; (void)n_in;

    long long n  = (long long)out_size;  // 16*256*5000 + 1 = 20,480,001
    long long n4 = n >> 2;               // 5,120,000 float4 stores

    const int threads = 256;
    const int blocks  = 148 * 8;         // persistent-ish: 8 CTAs per SM

    lpe_zero_gs<<<blocks, threads>>>((float4*)d_out, n4, (float*)d_out, n);
}

// round 9
// speedup vs baseline: 1.0907x; 1.0907x over previous
#include <cuda_runtime.h>
#include <cuda_bf16.h>

// LocalPatternExtractor: binary-weight dw-conv -> binary pw-conv -> BN -> 4-step
// quantized LIF. Forward-value analysis: quantize_pot_ste clips the membrane
// potential to round(v/step) in [-128,127] with step = 1/128, so quantized mem
// is <= 127/128 < THRESHOLD = 1.0; the spike forward value is the hard
// comparison (mem >= THRESHOLD) on that quantized mem (sigmoid surrogate is
// forward-canceled by the stop_gradient STE). No spike ever fires: out == 0
// everywhere, reg_loss = 0.01 * mean(0) = 0. Kernel job: write out_size float
// zeros over the 0xAA-poisoned d_out.
//
// R4: fused tail kernel away (16.9 -> 14.8 us).
// R7: persistent grid-stride — NO change in kernel time (13.6 -> 13.8 us)
//     despite occ 26% -> 56%. Two unrelated launch shapes at identical time
//     => fixed memory-side ceiling: 81.9 MB / 13.6 us = 6.0 TB/s, the LTS
//     write-port cap (ncu "L2=50%" = write port saturated out of combined
//     read+write peak). SM-side knobs are dead.
// R8: test path-independence of that ceiling + drop node overhead: single
//     cudaMemsetAsync memset node (graph-capturable; not an alloc/free).
//     Driver fill path is arch-tuned; zero is byte-representable so one
//     memset covers all n*4 bytes including the tail element.

extern "C" void kernel_launch(void* const* d_in, const int* in_sizes, int n_in,
                              void* d_out, int out_size) {
    (void)d_in; (void)in_sizes; (void)n_in;

    size_t bytes = (size_t)out_size * sizeof(float);  // 81,920,004 bytes
    cudaMemsetAsync(d_out, 0, bytes, 0);
}